// round 1
// baseline (speedup 1.0000x reference)
#include <cuda_runtime.h>

#define BATCH 8
#define CIN   512
#define COUT  512
#define WDIM  512
#define HH    64
#define WW    64

#define CI_CHUNK 8
#define XSTRIDE  20   // padded row stride for x smem (float4-aligned, conflict-light)
#define WSTRIDE  68   // padded row stride for w smem (16B-aligned, breaks 32-way STS conflict)

// Scratch (device globals: allocation-free per harness rules)
__device__ float g_style[BATCH * CIN];                      // 16 KB
__device__ float g_wmod[(size_t)BATCH * COUT * CIN * 9];    // 75.5 MB

// ---------------------------------------------------------------------------
// Kernel 1: styles  s[b][ci] = dot(w[b], affine_w[ci]) + affine_b[ci] + 1
// ---------------------------------------------------------------------------
__global__ void style_kernel(const float* __restrict__ w,
                             const float* __restrict__ aw,
                             const float* __restrict__ ab) {
    int warp = (blockIdx.x * blockDim.x + threadIdx.x) >> 5;   // 0..4095
    int lane = threadIdx.x & 31;
    int b  = warp >> 9;
    int ci = warp & 511;
    const float* wr = w  + (size_t)b  * WDIM;
    const float* ar = aw + (size_t)ci * WDIM;
    float s = 0.f;
#pragma unroll
    for (int k = 0; k < WDIM / 32; k++)
        s += wr[lane + k * 32] * ar[lane + k * 32];
#pragma unroll
    for (int o = 16; o; o >>= 1)
        s += __shfl_xor_sync(0xffffffffu, s, o);
    if (lane == 0)
        g_style[b * CIN + ci] = s + ab[ci] + 1.0f;
}

// ---------------------------------------------------------------------------
// Kernel 2: modulate + demodulate
//   w_mod[b][co][ci][t] = weight[co][ci][t] * s[b][ci] * rsqrt(sumsq + 1e-8)
// One block per (b, co); 4608 = 18 * 256 elements.
// ---------------------------------------------------------------------------
__global__ void modw_kernel(const float* __restrict__ weight) {
    int bco = blockIdx.x;
    int b   = bco >> 9;
    int co  = bco & 511;
    int tid = threadIdx.x;

    const float* wbase = weight + (size_t)co * CIN * 9;
    const float* sb    = g_style + b * CIN;

    float v[18];
    float ss = 0.f;
#pragma unroll
    for (int i = 0; i < 18; i++) {
        int idx = tid + i * 256;       // 0..4607, coalesced
        int ci  = idx / 9;
        float val = wbase[idx] * sb[ci];
        v[i] = val;
        ss += val * val;
    }
#pragma unroll
    for (int o = 16; o; o >>= 1)
        ss += __shfl_xor_sync(0xffffffffu, ss, o);

    __shared__ float red[8];
    if ((tid & 31) == 0) red[tid >> 5] = ss;
    __syncthreads();
    float tot = 0.f;
#pragma unroll
    for (int i = 0; i < 8; i++) tot += red[i];
    float dmul = rsqrtf(tot + 1e-8f);

    float* out = g_wmod + (size_t)bco * CIN * 9;
#pragma unroll
    for (int i = 0; i < 18; i++)
        out[tid + i * 256] = v[i] * dmul;
}

// ---------------------------------------------------------------------------
// Kernel 3: direct conv, register-blocked, f32x2 packed FMA.
// Grid: (16 spatial tiles, 8 cout tiles, 8 batch). Block: 256 threads.
// Thread owns 4 horizontal pixels x 16 couts, paired along cout for fma.f32x2.
// ---------------------------------------------------------------------------
__global__ __launch_bounds__(256, 2)
void conv_kernel(const float* __restrict__ x,
                 const float* __restrict__ noise,
                 const float* __restrict__ bias,
                 float* __restrict__ out) {
    __shared__ __align__(16) float xs[CI_CHUNK * 18 * XSTRIDE];   // 11.5 KB
    __shared__ __align__(16) float ws[CI_CHUNK * 9 * WSTRIDE];    // 19.6 KB

    int tid  = threadIdx.x;
    int b    = blockIdx.z;
    int cot  = blockIdx.y;
    int trow = blockIdx.x >> 2;
    int tcol = blockIdx.x & 3;
    int co_base = cot * 64;

    int cog  = tid & 3;        // 4 cout groups of 16
    int pxg  = tid >> 2;       // 64 pixel groups of 4
    int row  = pxg >> 2;       // 0..15
    int colg = pxg & 3;
    int c0   = colg * 4;       // local col base

    unsigned long long acc[4][8];  // [pixel j][cout pair p] — (co=2p, co=2p+1)
#pragma unroll
    for (int j = 0; j < 4; j++)
#pragma unroll
        for (int p = 0; p < 8; p++) acc[j][p] = 0ull;

    const float* xb = x + (size_t)b * CIN * HH * WW;
    int y0 = trow * 16 - 1;
    int x0 = tcol * 16 - 1;

    for (int cc = 0; cc < CIN / CI_CHUNK; cc++) {
        int ci0 = cc * CI_CHUNK;
        __syncthreads();

        // ---- load w tile: 64co x 8ci x 9 = 4608 = 18*256 ----
        {
            const float* wg = g_wmod +
                (((size_t)b * COUT + co_base) * CIN + ci0) * 9;
#pragma unroll
            for (int i = 0; i < 18; i++) {
                int t   = tid + i * 256;
                int coL = t / 72;
                int rem = t - coL * 72;            // ciL*9 + tap
                ws[rem * WSTRIDE + coL] = wg[(size_t)coL * (CIN * 9) + rem];
            }
        }

        // ---- load x patch: 8ci x 18x18 (zero-padded) ----
        if (tid < CI_CHUNK * 18) {
            int ciL = tid / 18;
            int r   = tid - ciL * 18;
            int gy  = y0 + r;
            float* dst = &xs[(ciL * 18 + r) * XSTRIDE];
            if (gy < 0 || gy >= HH) {
#pragma unroll
                for (int c = 0; c < 18; c++) dst[c] = 0.f;
            } else {
                const float* src = xb + ((size_t)(ci0 + ciL) * HH + gy) * WW;
#pragma unroll
                for (int c = 0; c < 18; c++) {
                    int gx = x0 + c;
                    dst[c] = (gx >= 0 && gx < WW) ? src[gx] : 0.f;
                }
            }
        }
        __syncthreads();

        // ---- compute ----
#pragma unroll
        for (int ciL = 0; ciL < CI_CHUNK; ciL++) {
#pragma unroll
            for (int dy = 0; dy < 3; dy++) {
                const float* xr = &xs[(ciL * 18 + row + dy) * XSTRIDE + c0];
                float4 xa  = *(const float4*)xr;
                float2 xb2 = *(const float2*)(xr + 4);
                float xv[6] = {xa.x, xa.y, xa.z, xa.w, xb2.x, xb2.y};
                unsigned long long xd[6];
#pragma unroll
                for (int k = 0; k < 6; k++) {
                    unsigned int u = __float_as_uint(xv[k]);
                    asm("mov.b64 %0, {%1, %1};" : "=l"(xd[k]) : "r"(u));
                }
#pragma unroll
                for (int dx = 0; dx < 3; dx++) {
                    const float* wr =
                        &ws[(ciL * 9 + dy * 3 + dx) * WSTRIDE + cog * 16];
                    ulonglong2 w01 = *(const ulonglong2*)(wr);
                    ulonglong2 w23 = *(const ulonglong2*)(wr + 4);
                    ulonglong2 w45 = *(const ulonglong2*)(wr + 8);
                    ulonglong2 w67 = *(const ulonglong2*)(wr + 12);
                    unsigned long long wp[8] = {w01.x, w01.y, w23.x, w23.y,
                                                w45.x, w45.y, w67.x, w67.y};
#pragma unroll
                    for (int j = 0; j < 4; j++) {
#pragma unroll
                        for (int p = 0; p < 8; p++) {
                            asm("fma.rn.f32x2 %0, %1, %2, %0;"
                                : "+l"(acc[j][p])
                                : "l"(xd[dx + j]), "l"(wp[p]));
                        }
                    }
                }
            }
        }
    }

    // ---- epilogue: +noise +bias, leaky relu 0.2, float4 stores ----
    int gy = trow * 16 + row;
    int gx = tcol * 16 + c0;
#pragma unroll
    for (int p = 0; p < 8; p++) {
#pragma unroll
        for (int h = 0; h < 2; h++) {
            int co = co_base + cog * 16 + p * 2 + h;
            float bv = bias[co];
            size_t oidx = (((size_t)b * COUT + co) * HH + gy) * WW + gx;
            float4 nz = *(const float4*)(noise + oidx);
            float vals[4];
#pragma unroll
            for (int j = 0; j < 4; j++) {
                float2 f2;
                unsigned long long a = acc[j][p];
                f2 = *reinterpret_cast<float2*>(&a);
                vals[j] = h ? f2.y : f2.x;
            }
            float4 o;
            o.x = vals[0] + nz.x + bv;
            o.y = vals[1] + nz.y + bv;
            o.z = vals[2] + nz.z + bv;
            o.w = vals[3] + nz.w + bv;
            o.x = (o.x >= 0.f) ? o.x : 0.2f * o.x;
            o.y = (o.y >= 0.f) ? o.y : 0.2f * o.y;
            o.z = (o.z >= 0.f) ? o.z : 0.2f * o.z;
            o.w = (o.w >= 0.f) ? o.w : 0.2f * o.w;
            *(float4*)(out + oidx) = o;
        }
    }
}

// ---------------------------------------------------------------------------
// Launch
// Inputs (metadata order): 0:x 1:w 2:noise 3:weight 4:affine_w 5:affine_b 6:bias
// ---------------------------------------------------------------------------
extern "C" void kernel_launch(void* const* d_in, const int* in_sizes, int n_in,
                              void* d_out, int out_size) {
    const float* x        = (const float*)d_in[0];
    const float* w        = (const float*)d_in[1];
    const float* noise    = (const float*)d_in[2];
    const float* weight   = (const float*)d_in[3];
    const float* affine_w = (const float*)d_in[4];
    const float* affine_b = (const float*)d_in[5];
    const float* bias     = (const float*)d_in[6];
    float* out = (float*)d_out;

    style_kernel<<<512, 256>>>(w, affine_w, affine_b);
    modw_kernel<<<BATCH * COUT, 256>>>(weight);
    dim3 grid(16, COUT / 64, BATCH);
    conv_kernel<<<grid, 256>>>(x, noise, bias, out);
}

// round 3
// speedup vs baseline: 5.0683x; 5.0683x over previous
#include <cuda_runtime.h>
#include <cuda_bf16.h>
#include <cstdint>

#define BATCH 8
#define CIN   512
#define COUT  512
#define WDIM  512
#define HH    64
#define WW    64

#define PADW  66
#define NPIX  (PADW * PADW)    // 4356
#define KDIM  4608             // 9 taps * 512 ci
#define NKB   72               // K blocks of 64

// ---------------- device global scratch ------------------------------------
__device__ float         g_style[BATCH * CIN];
__device__ __nv_bfloat16 g_wAhi[(size_t)BATCH * COUT * KDIM];
__device__ __nv_bfloat16 g_wAlo[(size_t)BATCH * COUT * KDIM];
__device__ __nv_bfloat16 g_xthi[(size_t)BATCH * NPIX * CIN];
__device__ __nv_bfloat16 g_xtlo[(size_t)BATCH * NPIX * CIN];

// ---------------- helpers ---------------------------------------------------
__device__ __forceinline__ uint32_t smem_u32(const void* p) {
    uint32_t a;
    asm("{ .reg .u64 t; cvta.to.shared.u64 t, %1; cvt.u32.u64 %0, t; }"
        : "=r"(a) : "l"(p));
    return a;
}
__device__ __forceinline__ void cp16(uint32_t dst, const void* src) {
    asm volatile("cp.async.cg.shared.global [%0], [%1], 16;" :: "r"(dst), "l"(src));
}
#define CP_COMMIT() asm volatile("cp.async.commit_group;" ::: "memory")
#define CP_WAIT1()  asm volatile("cp.async.wait_group 1;" ::: "memory")
#define CP_WAIT0()  asm volatile("cp.async.wait_group 0;" ::: "memory")

__device__ __forceinline__ void ldm4(uint32_t addr, uint32_t r[4]) {
    asm volatile("ldmatrix.sync.aligned.m8n8.x4.shared.b16 {%0,%1,%2,%3}, [%4];"
        : "=r"(r[0]), "=r"(r[1]), "=r"(r[2]), "=r"(r[3]) : "r"(addr));
}
__device__ __forceinline__ void mma_bf16(float* d, const uint32_t* a,
                                         uint32_t b0, uint32_t b1) {
    asm volatile("mma.sync.aligned.m16n8k16.row.col.f32.bf16.bf16.f32 "
        "{%0,%1,%2,%3}, {%4,%5,%6,%7}, {%8,%9}, {%0,%1,%2,%3};"
        : "+f"(d[0]), "+f"(d[1]), "+f"(d[2]), "+f"(d[3])
        : "r"(a[0]), "r"(a[1]), "r"(a[2]), "r"(a[3]), "r"(b0), "r"(b1));
}

// ---------------------------------------------------------------------------
// Kernel 1: styles
// ---------------------------------------------------------------------------
__global__ void style_kernel(const float* __restrict__ w,
                             const float* __restrict__ aw,
                             const float* __restrict__ ab) {
    int warp = (blockIdx.x * blockDim.x + threadIdx.x) >> 5;
    int lane = threadIdx.x & 31;
    int b = warp >> 9, ci = warp & 511;
    const float* wr = w + (size_t)b * WDIM;
    const float* ar = aw + (size_t)ci * WDIM;
    float s = 0.f;
#pragma unroll
    for (int k = 0; k < WDIM / 32; k++)
        s += wr[lane + k * 32] * ar[lane + k * 32];
#pragma unroll
    for (int o = 16; o; o >>= 1) s += __shfl_xor_sync(~0u, s, o);
    if (lane == 0) g_style[b * CIN + ci] = s + ab[ci] + 1.0f;
}

// ---------------------------------------------------------------------------
// Kernel 2: zero padded X buffers
// ---------------------------------------------------------------------------
__global__ void zerox_kernel() {
    size_t i = (size_t)blockIdx.x * blockDim.x + threadIdx.x;
    size_t stride = (size_t)gridDim.x * blockDim.x;
    uint4 z = {0, 0, 0, 0};
    uint4* ph = reinterpret_cast<uint4*>(g_xthi);
    uint4* pl = reinterpret_cast<uint4*>(g_xtlo);
    for (size_t o = i; o < 2230272u; o += stride) { ph[o] = z; pl[o] = z; }
}

// ---------------------------------------------------------------------------
// Kernel 3: transpose x -> channel-last padded bf16 hi/lo
// ---------------------------------------------------------------------------
__global__ void xpose_kernel(const float* __restrict__ x) {
    __shared__ float tile[64][65];
    int cib = blockIdx.x, y = blockIdx.y, b = blockIdx.z;
    int ci0 = cib * 64, tid = threadIdx.x;
    const float* src = x + (((size_t)b * CIN + ci0) * HH + y) * WW;
#pragma unroll
    for (int i = 0; i < 16; i++) {
        int o = tid + i * 256;
        tile[o >> 6][o & 63] = src[(size_t)(o >> 6) * (HH * WW) + (o & 63)];
    }
    __syncthreads();
#pragma unroll
    for (int i = 0; i < 16; i++) {
        int o = tid + i * 256;
        int xc = o >> 6, ciL = o & 63;
        float v = tile[ciL][xc];
        __nv_bfloat16 hi = __float2bfloat16_rn(v);
        __nv_bfloat16 lo = __float2bfloat16_rn(v - __bfloat162float(hi));
        size_t oi = ((size_t)b * NPIX + (size_t)(y + 1) * PADW + (xc + 1)) * CIN
                  + ci0 + ciL;
        g_xthi[oi] = hi;
        g_xtlo[oi] = lo;
    }
}

// ---------------------------------------------------------------------------
// Kernel 4: modulate + demodulate -> A [b][co][tap*512+ci] bf16 hi/lo
// ---------------------------------------------------------------------------
__global__ void modw2_kernel(const float* __restrict__ weight) {
    __shared__ float ws[KDIM];
    __shared__ float red[8];
    int b = blockIdx.x >> 9, co = blockIdx.x & 511;
    int tid = threadIdx.x;
    const float* wb = weight + (size_t)co * KDIM;
#pragma unroll
    for (int i = 0; i < 18; i++) ws[tid + i * 256] = wb[tid + i * 256];
    __syncthreads();
    float v[18], ss = 0.f;
#pragma unroll
    for (int i = 0; i < 18; i++) {
        int o = tid + i * 256;
        int ci = o & 511, tap = o >> 9;
        float val = ws[ci * 9 + tap] * g_style[b * CIN + ci];
        v[i] = val;
        ss += val * val;
    }
#pragma unroll
    for (int o = 16; o; o >>= 1) ss += __shfl_xor_sync(~0u, ss, o);
    if ((tid & 31) == 0) red[tid >> 5] = ss;
    __syncthreads();
    float tot = 0.f;
#pragma unroll
    for (int i = 0; i < 8; i++) tot += red[i];
    float d = rsqrtf(tot + 1e-8f);
    size_t base = (size_t)blockIdx.x * KDIM;
#pragma unroll
    for (int i = 0; i < 18; i++) {
        int o = tid + i * 256;
        float val = v[i] * d;
        __nv_bfloat16 hi = __float2bfloat16_rn(val);
        __nv_bfloat16 lo = __float2bfloat16_rn(val - __bfloat162float(hi));
        g_wAhi[base + o] = hi;
        g_wAlo[base + o] = lo;
    }
}

// ---------------------------------------------------------------------------
// Kernel 5: mma.sync implicit-GEMM conv
// CTA: 128 cout x 128 pixels (2 rows), K=4608 in 72 chunks of 64.
// SMEM stage (64KB): Ahi 16K | Alo 16K | Bhi 16K | Blo 16K. 3 stages = 192KB.
// Layout per plane: 128 rows x 128B, 16B unit c swizzled: c ^= (row & 7).
// ---------------------------------------------------------------------------
#define STG 65536
#define SMEM_BYTES (3 * STG)

__device__ __forceinline__ void load_stage(int kb, uint32_t sbase, int b,
                                           int co0, int y0, int tid) {
    int tap = kb >> 3, cib = kb & 7;
    int dy = tap / 3 - 1, dx = tap % 3 - 1;
    // A: 128 rows x 8 16B-cols per plane -> 1024 cp16 per plane
    const __nv_bfloat16* Ah = g_wAhi + (size_t)(b * COUT + co0) * KDIM + kb * 64;
    const __nv_bfloat16* Al = g_wAlo + (size_t)(b * COUT + co0) * KDIM + kb * 64;
#pragma unroll
    for (int i = 0; i < 4; i++) {
        int o = tid + i * 256;
        int r = o >> 3, c = o & 7;
        uint32_t d = (uint32_t)(r * 128 + ((c ^ (r & 7)) << 4));
        size_t g = (size_t)r * KDIM + c * 8;
        cp16(sbase + d, Ah + g);
        cp16(sbase + 16384 + d, Al + g);
    }
    // B: 128 pixel rows x 8 cols per plane
    const __nv_bfloat16* Xh = g_xthi + (size_t)b * NPIX * CIN + cib * 64;
    const __nv_bfloat16* Xl = g_xtlo + (size_t)b * NPIX * CIN + cib * 64;
#pragma unroll
    for (int i = 0; i < 4; i++) {
        int o = tid + i * 256;
        int r = o >> 3, c = o & 7;
        int yl = r >> 6, xc = r & 63;
        int prow = (y0 + yl + dy + 1) * PADW + (xc + dx + 1);
        size_t g = (size_t)prow * CIN + c * 8;
        uint32_t d = (uint32_t)(r * 128 + ((c ^ (r & 7)) << 4));
        cp16(sbase + 32768 + d, Xh + g);
        cp16(sbase + 49152 + d, Xl + g);
    }
}

__global__ void __launch_bounds__(256)
conv_mma_kernel(const float* __restrict__ noise,
                const float* __restrict__ bias,
                float* __restrict__ out) {
    extern __shared__ __align__(1024) char smem[];
    uint32_t sb = smem_u32(smem);
    int tid = threadIdx.x, wid = tid >> 5, lane = tid & 31;
    int pxt = blockIdx.x, cot = blockIdx.y, b = blockIdx.z;
    int co0 = cot * 128, y0 = pxt * 2;
    int wm = wid >> 2, wn = wid & 3;          // warp grid 2 x 4

    float acc[4][4][4];
#pragma unroll
    for (int i = 0; i < 4; i++)
#pragma unroll
        for (int j = 0; j < 4; j++)
#pragma unroll
            for (int q = 0; q < 4; q++) acc[i][j][q] = 0.f;

    // precomputed ldmatrix lane geometry
    int a_row = wm * 64 + ((lane >> 3) & 1) * 8 + (lane & 7);   // + mf*16
    int a_cc  = lane >> 4;                                       // + ks*2
    int b_row = wn * 32 + ((lane >> 4) & 1) * 8 + (lane & 7);   // + g*16
    int b_cc  = (lane >> 3) & 1;                                 // + ks*2

    load_stage(0, sb,           b, co0, y0, tid); CP_COMMIT();
    load_stage(1, sb + STG,     b, co0, y0, tid); CP_COMMIT();

    for (int kb = 0; kb < NKB; kb++) {
        int s = kb % 3;
        if (kb + 2 < NKB) CP_WAIT1(); else CP_WAIT0();
        __syncthreads();
        if (kb + 2 < NKB) {
            load_stage(kb + 2, sb + ((kb + 2) % 3) * STG, b, co0, y0, tid);
            CP_COMMIT();
        }
        uint32_t sA = sb + s * STG;
        uint32_t sB = sA + 32768;
#pragma unroll
        for (int ks = 0; ks < 4; ks++) {
            uint32_t Ah[4][4], Al[4][4], Bh[2][4], Bl[2][4];
#pragma unroll
            for (int mf = 0; mf < 4; mf++) {
                int r = a_row + mf * 16;
                int cc = a_cc + ks * 2;
                uint32_t ad = sA + r * 128 + ((cc ^ (r & 7)) << 4);
                ldm4(ad, Ah[mf]);
                ldm4(ad + 16384, Al[mf]);
            }
#pragma unroll
            for (int g = 0; g < 2; g++) {
                int r = b_row + g * 16;
                int cc = b_cc + ks * 2;
                uint32_t bd = sB + r * 128 + ((cc ^ (r & 7)) << 4);
                ldm4(bd, Bh[g]);
                ldm4(bd + 16384, Bl[g]);
            }
#pragma unroll
            for (int mf = 0; mf < 4; mf++)
#pragma unroll
                for (int nf = 0; nf < 4; nf++) {
                    int g = nf >> 1, h = (nf & 1) * 2;
                    mma_bf16(acc[mf][nf], Ah[mf], Bh[g][h], Bh[g][h + 1]);
                    mma_bf16(acc[mf][nf], Ah[mf], Bl[g][h], Bl[g][h + 1]);
                    mma_bf16(acc[mf][nf], Al[mf], Bh[g][h], Bh[g][h + 1]);
                }
        }
        __syncthreads();
    }

    // ---- epilogue ----
    int g4 = lane >> 2, tg = lane & 3;
    float bv[4][2];
#pragma unroll
    for (int mf = 0; mf < 4; mf++) {
        bv[mf][0] = bias[co0 + wm * 64 + mf * 16 + g4];
        bv[mf][1] = bias[co0 + wm * 64 + mf * 16 + g4 + 8];
    }
#pragma unroll
    for (int mf = 0; mf < 4; mf++)
#pragma unroll
        for (int nf = 0; nf < 4; nf++) {
            int nl = wn * 32 + nf * 8 + tg * 2;
            int y = y0 + (nl >> 6), xx = nl & 63;
#pragma unroll
            for (int h = 0; h < 2; h++) {
                int co = co0 + wm * 64 + mf * 16 + g4 + h * 8;
                size_t oi = ((size_t)(b * COUT + co) * HH + y) * WW + xx;
                float2 nz = *reinterpret_cast<const float2*>(noise + oi);
                float vx = acc[mf][nf][h * 2 + 0] + nz.x + bv[mf][h];
                float vy = acc[mf][nf][h * 2 + 1] + nz.y + bv[mf][h];
                vx = (vx >= 0.f) ? vx : 0.2f * vx;
                vy = (vy >= 0.f) ? vy : 0.2f * vy;
                *reinterpret_cast<float2*>(out + oi) = make_float2(vx, vy);
            }
        }
}

// ---------------------------------------------------------------------------
// Launch. Inputs: 0:x 1:w 2:noise 3:weight 4:affine_w 5:affine_b 6:bias
// ---------------------------------------------------------------------------
extern "C" void kernel_launch(void* const* d_in, const int* in_sizes, int n_in,
                              void* d_out, int out_size) {
    const float* x        = (const float*)d_in[0];
    const float* w        = (const float*)d_in[1];
    const float* noise    = (const float*)d_in[2];
    const float* weight   = (const float*)d_in[3];
    const float* affine_w = (const float*)d_in[4];
    const float* affine_b = (const float*)d_in[5];
    const float* bias     = (const float*)d_in[6];
    float* out = (float*)d_out;

    cudaFuncSetAttribute(conv_mma_kernel,
                         cudaFuncAttributeMaxDynamicSharedMemorySize, SMEM_BYTES);

    style_kernel<<<512, 256>>>(w, affine_w, affine_b);
    zerox_kernel<<<4356, 256>>>();
    xpose_kernel<<<dim3(8, 64, 8), 256>>>(x);
    modw2_kernel<<<BATCH * COUT, 256>>>(weight);
    conv_mma_kernel<<<dim3(32, 4, 8), 256, SMEM_BYTES>>>(noise, bias, out);
}

// round 4
// speedup vs baseline: 5.3199x; 1.0496x over previous
#include <cuda_runtime.h>
#include <cuda_bf16.h>
#include <cstdint>

#define BATCH 8
#define CIN   512
#define COUT  512
#define WDIM  512
#define HH    64
#define WW    64

#define PADW  66
#define NPIX  (PADW * PADW)    // 4356
#define KDIM  4608             // 9 taps * 512 ci
#define NKB   72               // K blocks of 64

// ---------------- device global scratch ------------------------------------
__device__ float         g_style[BATCH * CIN];
__device__ __nv_bfloat16 g_wAhi[(size_t)BATCH * COUT * KDIM];
__device__ __nv_bfloat16 g_wAlo[(size_t)BATCH * COUT * KDIM];
__device__ __nv_bfloat16 g_xthi[(size_t)BATCH * NPIX * CIN];
__device__ __nv_bfloat16 g_xtlo[(size_t)BATCH * NPIX * CIN];

// ---------------- helpers ---------------------------------------------------
__device__ __forceinline__ uint32_t smem_u32(const void* p) {
    uint32_t a;
    asm("{ .reg .u64 t; cvta.to.shared.u64 t, %1; cvt.u32.u64 %0, t; }"
        : "=r"(a) : "l"(p));
    return a;
}
__device__ __forceinline__ void cp16(uint32_t dst, const void* src) {
    asm volatile("cp.async.cg.shared.global [%0], [%1], 16;" :: "r"(dst), "l"(src));
}
#define CP_COMMIT() asm volatile("cp.async.commit_group;" ::: "memory")
#define CP_WAIT1()  asm volatile("cp.async.wait_group 1;" ::: "memory")
#define CP_WAIT0()  asm volatile("cp.async.wait_group 0;" ::: "memory")

__device__ __forceinline__ void ldm4(uint32_t addr, uint32_t r[4]) {
    asm volatile("ldmatrix.sync.aligned.m8n8.x4.shared.b16 {%0,%1,%2,%3}, [%4];"
        : "=r"(r[0]), "=r"(r[1]), "=r"(r[2]), "=r"(r[3]) : "r"(addr));
}
__device__ __forceinline__ void mma_bf16(float* d, const uint32_t* a,
                                         uint32_t b0, uint32_t b1) {
    asm volatile("mma.sync.aligned.m16n8k16.row.col.f32.bf16.bf16.f32 "
        "{%0,%1,%2,%3}, {%4,%5,%6,%7}, {%8,%9}, {%0,%1,%2,%3};"
        : "+f"(d[0]), "+f"(d[1]), "+f"(d[2]), "+f"(d[3])
        : "r"(a[0]), "r"(a[1]), "r"(a[2]), "r"(a[3]), "r"(b0), "r"(b1));
}

// ---------------------------------------------------------------------------
// Kernel A (launch #1): transpose x -> channel-last padded bf16 hi/lo,
// with border zeroing fused in (y==0 blocks zero the pad ring).
// grid (cib=8, y=64, b=8), 256 threads
// ---------------------------------------------------------------------------
__global__ void xpose_kernel(const float* __restrict__ x) {
    __shared__ float tile[64][65];
    int cib = blockIdx.x, y = blockIdx.y, b = blockIdx.z;
    int ci0 = cib * 64, tid = threadIdx.x;
    const float* src = x + (((size_t)b * CIN + ci0) * HH + y) * WW;
#pragma unroll
    for (int i = 0; i < 16; i++) {
        int o = tid + i * 256;
        tile[o >> 6][o & 63] = src[(size_t)(o >> 6) * (HH * WW) + (o & 63)];
    }

    // border zeroing: 260 pad-ring positions x 64 ci (only y==0 blocks)
    if (y == 0) {
        uint4 z = {0, 0, 0, 0};
        for (int o = tid; o < 260 * 8; o += 256) {
            int p = o >> 3, u = o & 7;
            int prow, pcol;
            if (p < 66)       { prow = 0;        pcol = p; }
            else if (p < 132) { prow = 65;       pcol = p - 66; }
            else if (p < 196) { prow = p - 131;  pcol = 0; }   // rows 1..64
            else              { prow = p - 195;  pcol = 65; }
            size_t idx = ((size_t)b * NPIX + (size_t)prow * PADW + pcol) * CIN
                       + ci0 + u * 8;
            *reinterpret_cast<uint4*>(g_xthi + idx) = z;
            *reinterpret_cast<uint4*>(g_xtlo + idx) = z;
        }
    }
    __syncthreads();
#pragma unroll
    for (int i = 0; i < 16; i++) {
        int o = tid + i * 256;
        int xc = o >> 6, ciL = o & 63;
        float v = tile[ciL][xc];
        __nv_bfloat16 hi = __float2bfloat16_rn(v);
        __nv_bfloat16 lo = __float2bfloat16_rn(v - __bfloat162float(hi));
        size_t oi = ((size_t)b * NPIX + (size_t)(y + 1) * PADW + (xc + 1)) * CIN
                  + ci0 + ciL;
        g_xthi[oi] = hi;
        g_xtlo[oi] = lo;
    }
}

// ---------------------------------------------------------------------------
// Kernel B (launch #2): styles
// ---------------------------------------------------------------------------
__global__ void style_kernel(const float* __restrict__ w,
                             const float* __restrict__ aw,
                             const float* __restrict__ ab) {
    int warp = (blockIdx.x * blockDim.x + threadIdx.x) >> 5;
    int lane = threadIdx.x & 31;
    int b = warp >> 9, ci = warp & 511;
    const float* wr = w + (size_t)b * WDIM;
    const float* ar = aw + (size_t)ci * WDIM;
    float s = 0.f;
#pragma unroll
    for (int k = 0; k < WDIM / 32; k++)
        s += wr[lane + k * 32] * ar[lane + k * 32];
#pragma unroll
    for (int o = 16; o; o >>= 1) s += __shfl_xor_sync(~0u, s, o);
    if (lane == 0) g_style[b * CIN + ci] = s + ab[ci] + 1.0f;
}

// ---------------------------------------------------------------------------
// Kernel C (launch #3): modulate + demodulate -> A [b][co][tap*512+ci] hi/lo
// ---------------------------------------------------------------------------
__global__ void modw2_kernel(const float* __restrict__ weight) {
    __shared__ float ws[KDIM];
    __shared__ float red[8];
    int b = blockIdx.x >> 9, co = blockIdx.x & 511;
    int tid = threadIdx.x;
    const float* wb = weight + (size_t)co * KDIM;
#pragma unroll
    for (int i = 0; i < 18; i++) ws[tid + i * 256] = wb[tid + i * 256];
    __syncthreads();
    float v[18], ss = 0.f;
#pragma unroll
    for (int i = 0; i < 18; i++) {
        int o = tid + i * 256;
        int ci = o & 511, tap = o >> 9;
        float val = ws[ci * 9 + tap] * g_style[b * CIN + ci];
        v[i] = val;
        ss += val * val;
    }
#pragma unroll
    for (int o = 16; o; o >>= 1) ss += __shfl_xor_sync(~0u, ss, o);
    if ((tid & 31) == 0) red[tid >> 5] = ss;
    __syncthreads();
    float tot = 0.f;
#pragma unroll
    for (int i = 0; i < 8; i++) tot += red[i];
    float d = rsqrtf(tot + 1e-8f);
    size_t base = (size_t)blockIdx.x * KDIM;
#pragma unroll
    for (int i = 0; i < 18; i++) {
        int o = tid + i * 256;
        float val = v[i] * d;
        __nv_bfloat16 hi = __float2bfloat16_rn(val);
        __nv_bfloat16 lo = __float2bfloat16_rn(val - __bfloat162float(hi));
        g_wAhi[base + o] = hi;
        g_wAlo[base + o] = lo;
    }
}

// ---------------------------------------------------------------------------
// Kernel D (launch #4 == ncu capture slot): mma.sync implicit-GEMM conv
// CTA: 128 cout x 128 pixels (2 rows), K=4608 in 72 chunks of 64.
// SMEM stage (64KB): Ahi 16K | Alo 16K | Bhi 16K | Blo 16K. 3 stages = 192KB.
// Single __syncthreads per K-iter (3-stage rotation makes trailing sync
// redundant: write target (k+2)%3 was last read at iter k-1, before this
// iter's top barrier).
// ---------------------------------------------------------------------------
#define STG 65536
#define SMEM_BYTES (3 * STG)

__device__ __forceinline__ void load_stage(int kb, uint32_t sbase, int b,
                                           int co0, int y0, int tid) {
    int tap = kb >> 3, cib = kb & 7;
    int dy = tap / 3 - 1, dx = tap % 3 - 1;
    const __nv_bfloat16* Ah = g_wAhi + (size_t)(b * COUT + co0) * KDIM + kb * 64;
    const __nv_bfloat16* Al = g_wAlo + (size_t)(b * COUT + co0) * KDIM + kb * 64;
#pragma unroll
    for (int i = 0; i < 4; i++) {
        int o = tid + i * 256;
        int r = o >> 3, c = o & 7;
        uint32_t d = (uint32_t)(r * 128 + ((c ^ (r & 7)) << 4));
        size_t g = (size_t)r * KDIM + c * 8;
        cp16(sbase + d, Ah + g);
        cp16(sbase + 16384 + d, Al + g);
    }
    const __nv_bfloat16* Xh = g_xthi + (size_t)b * NPIX * CIN + cib * 64;
    const __nv_bfloat16* Xl = g_xtlo + (size_t)b * NPIX * CIN + cib * 64;
#pragma unroll
    for (int i = 0; i < 4; i++) {
        int o = tid + i * 256;
        int r = o >> 3, c = o & 7;
        int yl = r >> 6, xc = r & 63;
        int prow = (y0 + yl + dy + 1) * PADW + (xc + dx + 1);
        size_t g = (size_t)prow * CIN + c * 8;
        uint32_t d = (uint32_t)(r * 128 + ((c ^ (r & 7)) << 4));
        cp16(sbase + 32768 + d, Xh + g);
        cp16(sbase + 49152 + d, Xl + g);
    }
}

__global__ void __launch_bounds__(256)
conv_mma_kernel(const float* __restrict__ noise,
                const float* __restrict__ bias,
                float* __restrict__ out) {
    extern __shared__ __align__(1024) char smem[];
    uint32_t sb = smem_u32(smem);
    int tid = threadIdx.x, wid = tid >> 5, lane = tid & 31;
    int pxt = blockIdx.x, cot = blockIdx.y, b = blockIdx.z;
    int co0 = cot * 128, y0 = pxt * 2;
    int wm = wid >> 2, wn = wid & 3;          // warp grid 2 x 4

    float acc[4][4][4];
#pragma unroll
    for (int i = 0; i < 4; i++)
#pragma unroll
        for (int j = 0; j < 4; j++)
#pragma unroll
            for (int q = 0; q < 4; q++) acc[i][j][q] = 0.f;

    int a_row = wm * 64 + ((lane >> 3) & 1) * 8 + (lane & 7);
    int a_cc  = lane >> 4;
    int b_row = wn * 32 + ((lane >> 4) & 1) * 8 + (lane & 7);
    int b_cc  = (lane >> 3) & 1;

    load_stage(0, sb,       b, co0, y0, tid); CP_COMMIT();
    load_stage(1, sb + STG, b, co0, y0, tid); CP_COMMIT();

#pragma unroll 3
    for (int kb = 0; kb < NKB; kb++) {
        if (kb < NKB - 2) CP_WAIT1(); else CP_WAIT0();
        __syncthreads();
        if (kb + 2 < NKB) {
            load_stage(kb + 2, sb + ((kb + 2) % 3) * STG, b, co0, y0, tid);
            CP_COMMIT();
        }
        uint32_t sA = sb + (kb % 3) * STG;
        uint32_t sB = sA + 32768;
#pragma unroll
        for (int ks = 0; ks < 4; ks++) {
            uint32_t Ah[4][4], Al[4][4], Bh[2][4], Bl[2][4];
#pragma unroll
            for (int mf = 0; mf < 4; mf++) {
                int r = a_row + mf * 16;
                int cc = a_cc + ks * 2;
                uint32_t ad = sA + r * 128 + ((cc ^ (r & 7)) << 4);
                ldm4(ad, Ah[mf]);
                ldm4(ad + 16384, Al[mf]);
            }
#pragma unroll
            for (int g = 0; g < 2; g++) {
                int r = b_row + g * 16;
                int cc = b_cc + ks * 2;
                uint32_t bd = sB + r * 128 + ((cc ^ (r & 7)) << 4);
                ldm4(bd, Bh[g]);
                ldm4(bd + 16384, Bl[g]);
            }
#pragma unroll
            for (int mf = 0; mf < 4; mf++)
#pragma unroll
                for (int nf = 0; nf < 4; nf++) {
                    int g = nf >> 1, h = (nf & 1) * 2;
                    mma_bf16(acc[mf][nf], Ah[mf], Bh[g][h], Bh[g][h + 1]);
                    mma_bf16(acc[mf][nf], Ah[mf], Bl[g][h], Bl[g][h + 1]);
                    mma_bf16(acc[mf][nf], Al[mf], Bh[g][h], Bh[g][h + 1]);
                }
        }
    }

    // ---- epilogue ----
    int g4 = lane >> 2, tg = lane & 3;
    float bv[4][2];
#pragma unroll
    for (int mf = 0; mf < 4; mf++) {
        bv[mf][0] = bias[co0 + wm * 64 + mf * 16 + g4];
        bv[mf][1] = bias[co0 + wm * 64 + mf * 16 + g4 + 8];
    }
#pragma unroll
    for (int mf = 0; mf < 4; mf++)
#pragma unroll
        for (int nf = 0; nf < 4; nf++) {
            int nl = wn * 32 + nf * 8 + tg * 2;
            int y = y0 + (nl >> 6), xx = nl & 63;
#pragma unroll
            for (int h = 0; h < 2; h++) {
                int co = co0 + wm * 64 + mf * 16 + g4 + h * 8;
                size_t oi = ((size_t)(b * COUT + co) * HH + y) * WW + xx;
                float2 nz = *reinterpret_cast<const float2*>(noise + oi);
                float vx = acc[mf][nf][h * 2 + 0] + nz.x + bv[mf][h];
                float vy = acc[mf][nf][h * 2 + 1] + nz.y + bv[mf][h];
                vx = (vx >= 0.f) ? vx : 0.2f * vx;
                vy = (vy >= 0.f) ? vy : 0.2f * vy;
                *reinterpret_cast<float2*>(out + oi) = make_float2(vx, vy);
            }
        }
}

// ---------------------------------------------------------------------------
// Launch. Inputs: 0:x 1:w 2:noise 3:weight 4:affine_w 5:affine_b 6:bias
// Order chosen so conv is absolute launch #4 (the ncu capture slot).
// ---------------------------------------------------------------------------
extern "C" void kernel_launch(void* const* d_in, const int* in_sizes, int n_in,
                              void* d_out, int out_size) {
    const float* x        = (const float*)d_in[0];
    const float* w        = (const float*)d_in[1];
    const float* noise    = (const float*)d_in[2];
    const float* weight   = (const float*)d_in[3];
    const float* affine_w = (const float*)d_in[4];
    const float* affine_b = (const float*)d_in[5];
    const float* bias     = (const float*)d_in[6];
    float* out = (float*)d_out;

    cudaFuncSetAttribute(conv_mma_kernel,
                         cudaFuncAttributeMaxDynamicSharedMemorySize, SMEM_BYTES);

    xpose_kernel<<<dim3(8, 64, 8), 256>>>(x);
    style_kernel<<<512, 256>>>(w, affine_w, affine_b);
    modw2_kernel<<<BATCH * COUT, 256>>>(weight);
    conv_mma_kernel<<<dim3(32, 4, 8), 256, SMEM_BYTES>>>(noise, bias, out);
}

// round 6
// speedup vs baseline: 15.0888x; 2.8363x over previous
#include <cuda_runtime.h>
#include <cuda_fp16.h>
#include <cstdint>

#define BATCH 8
#define CIN   512
#define COUT  512
#define WDIM  512
#define HH    64
#define WW    64

#define PADW  66
#define NPIX  (PADW * PADW)    // 4356
#define KDIM  4608             // 9 taps * 512 ci
#define NKB   72               // K blocks of 64

// ---------------- device global scratch ------------------------------------
__device__ float  g_style[BATCH * CIN];
__device__ __half g_wA[(size_t)BATCH * COUT * KDIM];   // 36 MB
__device__ __half g_xt[(size_t)BATCH * NPIX * CIN];    // 34 MB

// ---------------- helpers ---------------------------------------------------
__device__ __forceinline__ uint32_t smem_u32(const void* p) {
    uint32_t a;
    asm("{ .reg .u64 t; cvta.to.shared.u64 t, %1; cvt.u32.u64 %0, t; }"
        : "=r"(a) : "l"(p));
    return a;
}
__device__ __forceinline__ void cp16(uint32_t dst, const void* src) {
    asm volatile("cp.async.cg.shared.global [%0], [%1], 16;" :: "r"(dst), "l"(src));
}
#define CP_COMMIT() asm volatile("cp.async.commit_group;" ::: "memory")
#define CP_WAIT1()  asm volatile("cp.async.wait_group 1;" ::: "memory")
#define CP_WAIT0()  asm volatile("cp.async.wait_group 0;" ::: "memory")

__device__ __forceinline__ void ldm4(uint32_t addr, uint32_t r[4]) {
    asm volatile("ldmatrix.sync.aligned.m8n8.x4.shared.b16 {%0,%1,%2,%3}, [%4];"
        : "=r"(r[0]), "=r"(r[1]), "=r"(r[2]), "=r"(r[3]) : "r"(addr));
}
__device__ __forceinline__ void mma_f16(float* d, const uint32_t* a,
                                        uint32_t b0, uint32_t b1) {
    asm volatile("mma.sync.aligned.m16n8k16.row.col.f32.f16.f16.f32 "
        "{%0,%1,%2,%3}, {%4,%5,%6,%7}, {%8,%9}, {%0,%1,%2,%3};"
        : "+f"(d[0]), "+f"(d[1]), "+f"(d[2]), "+f"(d[3])
        : "r"(a[0]), "r"(a[1]), "r"(a[2]), "r"(a[3]), "r"(b0), "r"(b1));
}

// ---------------------------------------------------------------------------
// Kernel A (launch #1): transpose x -> channel-last padded fp16,
// border zeroing fused (y==0 blocks clear the pad ring).
// grid (cib=8, y=64, b=8), 256 threads
// ---------------------------------------------------------------------------
__global__ void xpose_kernel(const float* __restrict__ x) {
    __shared__ float tile[64][65];
    int cib = blockIdx.x, y = blockIdx.y, b = blockIdx.z;
    int ci0 = cib * 64, tid = threadIdx.x;
    const float* src = x + (((size_t)b * CIN + ci0) * HH + y) * WW;
#pragma unroll
    for (int i = 0; i < 16; i++) {
        int o = tid + i * 256;
        tile[o >> 6][o & 63] = src[(size_t)(o >> 6) * (HH * WW) + (o & 63)];
    }
    if (y == 0) {
        uint4 z = {0, 0, 0, 0};
        for (int o = tid; o < 260 * 8; o += 256) {
            int p = o >> 3, u = o & 7;
            int prow, pcol;
            if (p < 66)       { prow = 0;        pcol = p; }
            else if (p < 132) { prow = 65;       pcol = p - 66; }
            else if (p < 196) { prow = p - 131;  pcol = 0; }
            else              { prow = p - 195;  pcol = 65; }
            size_t idx = ((size_t)b * NPIX + (size_t)prow * PADW + pcol) * CIN
                       + ci0 + u * 8;
            *reinterpret_cast<uint4*>(g_xt + idx) = z;
        }
    }
    __syncthreads();
#pragma unroll
    for (int i = 0; i < 16; i++) {
        int o = tid + i * 256;
        int xc = o >> 6, ciL = o & 63;
        size_t oi = ((size_t)b * NPIX + (size_t)(y + 1) * PADW + (xc + 1)) * CIN
                  + ci0 + ciL;
        g_xt[oi] = __float2half_rn(tile[ciL][xc]);
    }
}

// ---------------------------------------------------------------------------
// Kernel B (launch #2): styles
// ---------------------------------------------------------------------------
__global__ void style_kernel(const float* __restrict__ w,
                             const float* __restrict__ aw,
                             const float* __restrict__ ab) {
    int warp = (blockIdx.x * blockDim.x + threadIdx.x) >> 5;
    int lane = threadIdx.x & 31;
    int b = warp >> 9, ci = warp & 511;
    const float* wr = w + (size_t)b * WDIM;
    const float* ar = aw + (size_t)ci * WDIM;
    float s = 0.f;
#pragma unroll
    for (int k = 0; k < WDIM / 32; k++)
        s += wr[lane + k * 32] * ar[lane + k * 32];
#pragma unroll
    for (int o = 16; o; o >>= 1) s += __shfl_xor_sync(~0u, s, o);
    if (lane == 0) g_style[b * CIN + ci] = s + ab[ci] + 1.0f;
}

// ---------------------------------------------------------------------------
// Kernel C (launch #3): modulate + demodulate -> A [b][co][tap*512+ci] fp16
// ---------------------------------------------------------------------------
__global__ void modw2_kernel(const float* __restrict__ weight) {
    __shared__ float ws[KDIM];
    __shared__ float red[8];
    int b = blockIdx.x >> 9, co = blockIdx.x & 511;
    int tid = threadIdx.x;
    const float* wb = weight + (size_t)co * KDIM;
#pragma unroll
    for (int i = 0; i < 18; i++) ws[tid + i * 256] = wb[tid + i * 256];
    __syncthreads();
    float v[18], ss = 0.f;
#pragma unroll
    for (int i = 0; i < 18; i++) {
        int o = tid + i * 256;
        int ci = o & 511, tap = o >> 9;
        float val = ws[ci * 9 + tap] * g_style[b * CIN + ci];
        v[i] = val;
        ss += val * val;
    }
#pragma unroll
    for (int o = 16; o; o >>= 1) ss += __shfl_xor_sync(~0u, ss, o);
    if ((tid & 31) == 0) red[tid >> 5] = ss;
    __syncthreads();
    float tot = 0.f;
#pragma unroll
    for (int i = 0; i < 8; i++) tot += red[i];
    float d = rsqrtf(tot + 1e-8f);
    size_t base = (size_t)blockIdx.x * KDIM;
#pragma unroll
    for (int i = 0; i < 18; i++) {
        int o = tid + i * 256;
        g_wA[base + o] = __float2half_rn(v[i] * d);
    }
}

// ---------------------------------------------------------------------------
// Kernel D (launch #4 == ncu capture slot): fp16 mma.sync implicit-GEMM conv
// CTA: 128 cout x 128 pixels (2 rows), K=4608 in 72 chunks of 64.
// Stage (32KB): A 16K | B 16K. 3 stages = 96KB -> 2 CTAs/SM, 16 warps/SM.
// ---------------------------------------------------------------------------
#define STG 32768
#define SMEM_BYTES (3 * STG)

__device__ __forceinline__ void load_stage(int kb, uint32_t sbase, int b,
                                           int co0, int y0, int tid) {
    int tap = kb >> 3, cib = kb & 7;
    int dy = tap / 3 - 1, dx = tap % 3 - 1;
    const __half* A = g_wA + (size_t)(b * COUT + co0) * KDIM + kb * 64;
#pragma unroll
    for (int i = 0; i < 4; i++) {
        int o = tid + i * 256;
        int r = o >> 3, c = o & 7;
        uint32_t d = (uint32_t)(r * 128 + ((c ^ (r & 7)) << 4));
        cp16(sbase + d, A + (size_t)r * KDIM + c * 8);
    }
    const __half* X = g_xt + (size_t)b * NPIX * CIN + cib * 64;
#pragma unroll
    for (int i = 0; i < 4; i++) {
        int o = tid + i * 256;
        int r = o >> 3, c = o & 7;
        int yl = r >> 6, xc = r & 63;
        int prow = (y0 + yl + dy + 1) * PADW + (xc + dx + 1);
        uint32_t d = (uint32_t)(r * 128 + ((c ^ (r & 7)) << 4));
        cp16(sbase + 16384 + d, X + (size_t)prow * CIN + c * 8);
    }
}

__global__ void __launch_bounds__(256, 2)
conv_mma_kernel(const float* __restrict__ noise,
                const float* __restrict__ bias,
                float* __restrict__ out) {
    extern __shared__ __align__(1024) char smem[];
    uint32_t sb = smem_u32(smem);
    int tid = threadIdx.x, wid = tid >> 5, lane = tid & 31;
    int pxt = blockIdx.x, cot = blockIdx.y, b = blockIdx.z;
    int co0 = cot * 128, y0 = pxt * 2;
    int wm = wid >> 2, wn = wid & 3;          // warp grid 2 x 4

    float acc[4][4][4];
#pragma unroll
    for (int i = 0; i < 4; i++)
#pragma unroll
        for (int j = 0; j < 4; j++)
#pragma unroll
            for (int q = 0; q < 4; q++) acc[i][j][q] = 0.f;

    int a_row = wm * 64 + ((lane >> 3) & 1) * 8 + (lane & 7);
    int a_cc  = lane >> 4;
    int b_row = wn * 32 + ((lane >> 4) & 1) * 8 + (lane & 7);
    int b_cc  = (lane >> 3) & 1;

    load_stage(0, sb,       b, co0, y0, tid); CP_COMMIT();
    load_stage(1, sb + STG, b, co0, y0, tid); CP_COMMIT();

#pragma unroll 3
    for (int kb = 0; kb < NKB; kb++) {
        if (kb < NKB - 2) CP_WAIT1(); else CP_WAIT0();
        __syncthreads();
        if (kb + 2 < NKB) {
            load_stage(kb + 2, sb + ((kb + 2) % 3) * STG, b, co0, y0, tid);
            CP_COMMIT();
        }
        uint32_t sA = sb + (kb % 3) * STG;
        uint32_t sB = sA + 16384;
#pragma unroll
        for (int ks = 0; ks < 4; ks++) {
            uint32_t Ar[4][4], Br[2][4];
#pragma unroll
            for (int mf = 0; mf < 4; mf++) {
                int r = a_row + mf * 16;
                int cc = a_cc + ks * 2;
                ldm4(sA + r * 128 + ((cc ^ (r & 7)) << 4), Ar[mf]);
            }
#pragma unroll
            for (int g = 0; g < 2; g++) {
                int r = b_row + g * 16;
                int cc = b_cc + ks * 2;
                ldm4(sB + r * 128 + ((cc ^ (r & 7)) << 4), Br[g]);
            }
#pragma unroll
            for (int mf = 0; mf < 4; mf++)
#pragma unroll
                for (int nf = 0; nf < 4; nf++) {
                    int g = nf >> 1, h = (nf & 1) * 2;
                    mma_f16(acc[mf][nf], Ar[mf], Br[g][h], Br[g][h + 1]);
                }
        }
    }

    // ---- epilogue ----
    int g4 = lane >> 2, tg = lane & 3;
    float bv[4][2];
#pragma unroll
    for (int mf = 0; mf < 4; mf++) {
        bv[mf][0] = bias[co0 + wm * 64 + mf * 16 + g4];
        bv[mf][1] = bias[co0 + wm * 64 + mf * 16 + g4 + 8];
    }
#pragma unroll
    for (int mf = 0; mf < 4; mf++)
#pragma unroll
        for (int nf = 0; nf < 4; nf++) {
            int nl = wn * 32 + nf * 8 + tg * 2;
            int y = y0 + (nl >> 6), xx = nl & 63;
#pragma unroll
            for (int h = 0; h < 2; h++) {
                int co = co0 + wm * 64 + mf * 16 + g4 + h * 8;
                size_t oi = ((size_t)(b * COUT + co) * HH + y) * WW + xx;
                float2 nz = *reinterpret_cast<const float2*>(noise + oi);
                float vx = acc[mf][nf][h * 2 + 0] + nz.x + bv[mf][h];
                float vy = acc[mf][nf][h * 2 + 1] + nz.y + bv[mf][h];
                vx = (vx >= 0.f) ? vx : 0.2f * vx;
                vy = (vy >= 0.f) ? vy : 0.2f * vy;
                *reinterpret_cast<float2*>(out + oi) = make_float2(vx, vy);
            }
        }
}

// ---------------------------------------------------------------------------
// Launch. Inputs: 0:x 1:w 2:noise 3:weight 4:affine_w 5:affine_b 6:bias
// ---------------------------------------------------------------------------
extern "C" void kernel_launch(void* const* d_in, const int* in_sizes, int n_in,
                              void* d_out, int out_size) {
    const float* x        = (const float*)d_in[0];
    const float* w        = (const float*)d_in[1];
    const float* noise    = (const float*)d_in[2];
    const float* weight   = (const float*)d_in[3];
    const float* affine_w = (const float*)d_in[4];
    const float* affine_b = (const float*)d_in[5];
    const float* bias     = (const float*)d_in[6];
    float* out = (float*)d_out;

    cudaFuncSetAttribute(conv_mma_kernel,
                         cudaFuncAttributeMaxDynamicSharedMemorySize, SMEM_BYTES);

    xpose_kernel<<<dim3(8, 64, 8), 256>>>(x);
    style_kernel<<<512, 256>>>(w, affine_w, affine_b);
    modw2_kernel<<<BATCH * COUT, 256>>>(weight);
    conv_mma_kernel<<<dim3(32, 4, 8), 256, SMEM_BYTES>>>(noise, bias, out);
}